// round 5
// baseline (speedup 1.0000x reference)
#include <cuda_runtime.h>
#include <cstdint>

// Problem constants
#define N_IMG 16384
#define SS 49
#define NCELL (N_IMG * SS)        // 802816 (= 32 * 25088)
#define F 30
#define THREADS 128
#define WPB 4                     // warps per block
#define GRID 592                  // 4 blocks/SM * 148 SMs
#define NTILE (NCELL / 32)        // 25088 warp-tiles of 32 cells
#define SLOT 62                   // floats per obj staging slot (60 data + 2 pad)

__device__ float g_partial[GRID];
__device__ unsigned int g_count;  // zero at load; last block resets each run

__global__ __launch_bounds__(THREADS) void loss_kernel(
        const float* __restrict__ preds,
        const float* __restrict__ targets,
        float* __restrict__ out) {
    __shared__ float buf[WPB][32 * SLOT];       // 31744 B staging
    __shared__ float warp_sums[WPB];
    __shared__ double dsum[WPB];
    __shared__ bool is_last;

    const int lane = threadIdx.x & 31;
    const int wid = threadIdx.x >> 5;
    float* wbuf = buf[wid];
    const int gw = blockIdx.x * WPB + wid;      // global warp id
    const int TW = GRID * WPB;                  // total warps = 2368

    float l = 0.0f;

    // Prefetch conf for first tile.
    float2 pconf = make_float2(0.f, 0.f);
    float tconf = 0.f;
    if (gw < NTILE) {
        long long cell = (long long)gw * 32 + lane;
        pconf = *(const float2*)(preds + cell * F + 20);
        tconf = __ldg(targets + cell * F + 20);   // t[21] == t[20] by construction
    }

    for (int t = gw; t < NTILE; t += TW) {
        const float2 pc_cur = pconf;
        const float tc_cur = tconf;

        // Prefetch next tile's conf (overlaps with obj processing below).
        int tn = t + TW;
        if (tn < NTILE) {
            long long cell = (long long)tn * 32 + lane;
            pconf = *(const float2*)(preds + cell * F + 20);
            tconf = __ldg(targets + cell * F + 20);
        }

        // Conf MSE term (always): NOOBJ * sum((p_conf - t_conf)^2), tc1 == tc0.
        float d0 = pc_cur.x - tc_cur, d1 = pc_cur.y - tc_cur;
        l += 0.5f * (d0 * d0 + d1 * d1);

        const unsigned mask = __ballot_sync(0xffffffffu, tc_cur > 0.0f);
        const long long tilebase = (long long)t * 32;

        // Cooperative staging of obj cells: whole warp loads one cell's 240 B
        // (30 lanes x float2), batched 8-deep so LDGs overlap.
        unsigned mm = mask;
        while (mm) {
            float2 v[8];
            int bs[8];
            int nb = 0;
#pragma unroll
            for (int u = 0; u < 8; u++) {
                if (mm) {
                    int b = __ffs(mm) - 1;
                    mm &= mm - 1;
                    bs[u] = b;
                    long long base = (tilebase + b) * F;
                    if (lane < 30) {
                        const float* src = (lane < 15)
                            ? (preds + base + 2 * lane)
                            : (targets + base + 2 * (lane - 15));
                        v[u] = *(const float2*)src;
                    }
                    nb = u + 1;
                }
            }
#pragma unroll
            for (int u = 0; u < 8; u++) {
                if (u < nb && lane < 30) {
                    // slot b: floats [0..30) = p cell, [30..60) = t cell
                    *(float2*)&wbuf[bs[u] * SLOT + 2 * lane] = v[u];
                }
            }
        }
        __syncwarp();

        // Owner lanes compute obj loss in parallel from their slot.
        if (tc_cur > 0.0f) {
            const float* s = &wbuf[lane * SLOT];

            float acc = 0.0f;
#pragma unroll
            for (int c = 0; c < 20; c++) {
                float d = s[c] - s[30 + c];
                acc += d * d;
            }
            l += acc;

            float iou0, iou1;
#pragma unroll
            for (int b2 = 0; b2 < 2; b2++) {
                const float* pb = s + 22 + 4 * b2;       // p box
                const float* tb = s + 52 + 4 * b2;       // t box
                float xA = fmaxf(pb[0] - pb[2] * 0.5f, tb[0] - tb[2] * 0.5f);
                float yA = fmaxf(pb[1] - pb[3] * 0.5f, tb[1] - tb[3] * 0.5f);
                float xB = fminf(pb[0] + pb[2] * 0.5f, tb[0] + tb[2] * 0.5f);
                float yB = fminf(pb[1] + pb[3] * 0.5f, tb[1] + tb[3] * 0.5f);
                float inter = fmaxf(0.0f, xB - xA) * fmaxf(0.0f, yB - yA);
                float areaA = pb[2] * pb[3];
                float areaB = tb[2] * tb[3];
                float iou = inter / (areaA + areaB - inter);
                if (b2 == 0) iou0 = iou; else iou1 = iou;
            }
            int best = (iou1 > iou0) ? 1 : 0;           // argmax, tie -> 0

            float pcv = best ? pc_cur.y : pc_cur.x;     // responsible conf (target = 1)
            float dc = pcv - 1.0f;
            l += 0.5f * dc * dc;

            const float* pb = s + 22 + 4 * best;
            const float* tb = s + 52 + 4 * best;
            float dx = pb[0] - tb[0];
            float dy = pb[1] - tb[1];
            float dw = sqrtf(pb[2]) - sqrtf(tb[2]);
            float dh = sqrtf(pb[3]) - sqrtf(tb[3]);
            l += 5.0f * (dx * dx + dy * dy + dw * dw + dh * dh);
        }
        __syncwarp();   // owners done reading slots before next tile overwrites
    }

    // Intra-block reduction.
#pragma unroll
    for (int off = 16; off > 0; off >>= 1)
        l += __shfl_down_sync(0xffffffffu, l, off);
    if (lane == 0)
        warp_sums[wid] = l;
    __syncthreads();

    if (threadIdx.x == 0) {
        float blk = warp_sums[0] + warp_sums[1] + warp_sums[2] + warp_sums[3];
        g_partial[blockIdx.x] = blk;
        __threadfence();
        unsigned int old = atomicAdd(&g_count, 1u);
        is_last = (old == GRID - 1);
    }
    __syncthreads();

    // Last block reduces all partials in double and writes the result.
    if (is_last) {
        double acc = 0.0;
        for (int i = threadIdx.x; i < GRID; i += THREADS)
            acc += (double)__ldcg(&g_partial[i]);
#pragma unroll
        for (int off = 16; off > 0; off >>= 1)
            acc += __shfl_down_sync(0xffffffffu, acc, off);
        if (lane == 0)
            dsum[wid] = acc;
        __syncthreads();
        if (threadIdx.x == 0) {
            double total = dsum[0] + dsum[1] + dsum[2] + dsum[3];
            out[0] = (float)(total / (double)N_IMG);
            __threadfence();
            g_count = 0;  // reset for next graph replay
        }
    }
}

extern "C" void kernel_launch(void* const* d_in, const int* in_sizes, int n_in,
                              void* d_out, int out_size) {
    const float* preds = (const float*)d_in[0];
    const float* targets = (const float*)d_in[1];
    float* out = (float*)d_out;

    loss_kernel<<<GRID, THREADS>>>(preds, targets, out);
}

// round 6
// speedup vs baseline: 1.4830x; 1.4830x over previous
#include <cuda_runtime.h>
#include <cstdint>

// Problem constants
#define N_IMG 16384
#define SS 49
#define NCELL (N_IMG * SS)              // 802816
#define F 30
#define CPC 128                         // cells per chunk
#define NCHUNK (NCELL / CPC)            // 6272
#define THREADS 128
#define GRID 444                        // 3 blocks/SM * 148 SMs
#define STAGES 2

#define CHUNK_FLOATS (CPC * F)          // 3840 floats
#define CHUNK_BYTES (CHUNK_FLOATS * 4)  // 15360 B per tensor
#define TX_BYTES (2 * CHUNK_BYTES)      // 30720 B per chunk
#define DYN_SMEM (STAGES * TX_BYTES)    // 61440 B

__device__ float g_partial[GRID];
__device__ unsigned int g_count;        // zero at load; last block resets each run
__device__ unsigned int g_ticket;       // dynamic chunk scheduler; reset each run

__device__ __forceinline__ uint32_t smem_u32(const void* p) {
    return (uint32_t)__cvta_generic_to_shared(p);
}

#define MBAR_WAIT(bar, parity) do {                                           \
    asm volatile(                                                             \
        "{\n\t.reg .pred P1;\n\t"                                             \
        "WAIT_%=:\n\t"                                                        \
        "mbarrier.try_wait.parity.acquire.cta.shared::cta.b64 P1, [%0], %1, 0x989680;\n\t" \
        "@P1 bra.uni DONE_%=;\n\t"                                            \
        "bra.uni WAIT_%=;\n\t"                                                \
        "DONE_%=:\n\t}"                                                       \
        :: "r"(bar), "r"(parity) : "memory");                                 \
} while (0)

__global__ __launch_bounds__(THREADS) void loss_kernel(
        const float* __restrict__ preds,
        const float* __restrict__ targets,
        float* __restrict__ out) {
    extern __shared__ float smem[];     // [STAGES][preds 3840 | targets 3840]
    __shared__ __align__(8) unsigned long long mbar[STAGES];
    __shared__ int s_chunk[STAGES];     // chunk id resident/incoming in each stage
    __shared__ float warp_sums[THREADS / 32];
    __shared__ double dsum[THREADS / 32];
    __shared__ bool is_last;

    const int tid = threadIdx.x;

    if (tid == 0) {
#pragma unroll
        for (int s = 0; s < STAGES; s++)
            asm volatile("mbarrier.init.shared.b64 [%0], 1;"
                         :: "r"(smem_u32(&mbar[s])) : "memory");
    }
    __syncthreads();

    auto issue = [&](int c, int buf) {
        uint32_t bar = smem_u32(&mbar[buf]);
        asm volatile("mbarrier.arrive.expect_tx.shared.b64 _, [%0], %1;"
                     :: "r"(bar), "r"((uint32_t)TX_BYTES) : "memory");
        uint32_t dstp = smem_u32(smem) + buf * TX_BYTES;
        uint32_t dstt = dstp + CHUNK_BYTES;
        const float* srcp = preds + (long long)c * CHUNK_FLOATS;
        const float* srct = targets + (long long)c * CHUNK_FLOATS;
        asm volatile("cp.async.bulk.shared::cta.global.mbarrier::complete_tx::bytes [%0], [%1], %2, [%3];"
                     :: "r"(dstp), "l"(srcp), "r"((uint32_t)CHUNK_BYTES), "r"(bar) : "memory");
        asm volatile("cp.async.bulk.shared::cta.global.mbarrier::complete_tx::bytes [%0], [%1], %2, [%3];"
                     :: "r"(dstt), "l"(srct), "r"((uint32_t)CHUNK_BYTES), "r"(bar) : "memory");
    };

    // Prologue: grab and issue one chunk per stage.
    if (tid == 0) {
#pragma unroll
        for (int s = 0; s < STAGES; s++) {
            int c = (int)atomicAdd(&g_ticket, 1u);
            s_chunk[s] = c;
            if (c < NCHUNK) issue(c, s);
        }
    }
    __syncthreads();

    float l = 0.0f;
    int buf = 0, phs = 0;
    for (;;) {
        const int c = s_chunk[buf];
        if (c >= NCHUNK) break;
        MBAR_WAIT(smem_u32(&mbar[buf]), phs);

        // Cell records as float2 (stride 120 B -> conflict-free LDS.64).
        const float2* p2 = (const float2*)(smem + buf * 2 * CHUNK_FLOATS + tid * F);
        const float2* t2 = (const float2*)((const float*)p2 + CHUNK_FLOATS);

        // conf term (always): j=10 holds fields 20,21; t[21] == t[20].
        float2 pc = p2[10];
        float2 tc = t2[10];
        float d0 = pc.x - tc.x, d1 = pc.y - tc.y;
        l += 0.5f * (d0 * d0 + d1 * d1);

        if (tc.x > 0.0f) {  // obj cell: read the rest of the record
            float acc = 0.0f;
#pragma unroll
            for (int j = 0; j < 10; j++) {      // class probs (fields 0..19)
                float2 a = p2[j], b = t2[j];
                float dx = a.x - b.x, dy = a.y - b.y;
                acc += dx * dx + dy * dy;
            }
            l += acc;

            // boxes: b=0 -> j 11(x,y),12(w,h); b=1 -> j 13,14
            float iou[2];
#pragma unroll
            for (int b = 0; b < 2; b++) {
                float2 pxy = p2[11 + 2 * b], pwh = p2[12 + 2 * b];
                float2 txy = t2[11 + 2 * b], twh = t2[12 + 2 * b];
                float xA = fmaxf(pxy.x - pwh.x * 0.5f, txy.x - twh.x * 0.5f);
                float yA = fmaxf(pxy.y - pwh.y * 0.5f, txy.y - twh.y * 0.5f);
                float xB = fminf(pxy.x + pwh.x * 0.5f, txy.x + twh.x * 0.5f);
                float yB = fminf(pxy.y + pwh.y * 0.5f, txy.y + twh.y * 0.5f);
                float inter = fmaxf(0.0f, xB - xA) * fmaxf(0.0f, yB - yA);
                float areaA = pwh.x * pwh.y;
                float areaB = twh.x * twh.y;
                iou[b] = inter / (areaA + areaB - inter);
            }
            int best = (iou[1] > iou[0]) ? 1 : 0;   // argmax, tie -> 0

            float pcv = best ? pc.y : pc.x;          // responsible conf (target 1)
            float dc = pcv - 1.0f;
            l += 0.5f * dc * dc;

            float2 pxy = p2[11 + 2 * best], pwh = p2[12 + 2 * best];
            float2 txy = t2[11 + 2 * best], twh = t2[12 + 2 * best];
            float dx = pxy.x - txy.x;
            float dy = pxy.y - txy.y;
            float dw = sqrtf(pwh.x) - sqrtf(twh.x);
            float dh = sqrtf(pwh.y) - sqrtf(twh.y);
            l += 5.0f * (dx * dx + dy * dy + dw * dw + dh * dh);
        }

        __syncthreads();   // everyone done reading stage `buf`

        if (tid == 0) {    // grab next chunk dynamically and refill this stage
            int cn = (int)atomicAdd(&g_ticket, 1u);
            s_chunk[buf] = cn;
            if (cn < NCHUNK) issue(cn, buf);
        }
        // s_chunk[buf] publication to other threads is ordered by the
        // NEXT iteration's __syncthreads before it is read again.

        if (++buf == STAGES) { buf = 0; phs ^= 1; }
    }

    // Intra-block reduction.
#pragma unroll
    for (int off = 16; off > 0; off >>= 1)
        l += __shfl_down_sync(0xffffffffu, l, off);
    if ((tid & 31) == 0)
        warp_sums[tid >> 5] = l;
    __syncthreads();

    if (tid == 0) {
        float blk = warp_sums[0] + warp_sums[1] + warp_sums[2] + warp_sums[3];
        g_partial[blockIdx.x] = blk;
        __threadfence();
        unsigned int old = atomicAdd(&g_count, 1u);
        is_last = (old == GRID - 1);
    }
    __syncthreads();

    if (is_last) {
        double acc = 0.0;
        for (int i = tid; i < GRID; i += THREADS)
            acc += (double)__ldcg(&g_partial[i]);
#pragma unroll
        for (int off = 16; off > 0; off >>= 1)
            acc += __shfl_down_sync(0xffffffffu, acc, off);
        if ((tid & 31) == 0)
            dsum[tid >> 5] = acc;
        __syncthreads();
        if (tid == 0) {
            double total = dsum[0] + dsum[1] + dsum[2] + dsum[3];
            out[0] = (float)(total / (double)N_IMG);
            __threadfence();
            g_count = 0;
            g_ticket = 0;   // reset scheduler for next graph replay
        }
    }
}

extern "C" void kernel_launch(void* const* d_in, const int* in_sizes, int n_in,
                              void* d_out, int out_size) {
    const float* preds = (const float*)d_in[0];
    const float* targets = (const float*)d_in[1];
    float* out = (float*)d_out;

    cudaFuncSetAttribute(loss_kernel, cudaFuncAttributeMaxDynamicSharedMemorySize, DYN_SMEM);
    loss_kernel<<<GRID, THREADS, DYN_SMEM>>>(preds, targets, out);
}